// round 14
// baseline (speedup 1.0000x reference)
#include <cuda_runtime.h>
#include <cuda_bf16.h>
#include <cstdint>
#include <cstring>

// DynamicRouting: grouped 1x1 conv via mma.sync (HMMA bf16 3-pass fp32 split).
// con[g][o][p] lives ENTIRELY in registers (acc[8][4][4] per thread); routing
// epilogue uses per-pixel Gram matrices exchanged via an 18KB smem buffer.

#define G   8
#define FO  64
#define FI  64
#define HW  4096
#define C   512
#define BSZ 32
#define TP  64
#define NTHREADS 256

// smem: [gram 2*64*36 floats = 18432B][buf0 32KB][buf1 32KB]
#define OFF_BUF 18432
#define BUFSZ   32768
#define AHI 0
#define ALO 8192
#define BHI 16384
#define BLO 24576
#define SMEM_TOTAL (OFF_BUF + 2*BUFSZ)   // 83968 B

// packed weights: per group 16KB = [hi 8KB | lo 8KB], swizzled B-tile layout
__device__ __align__(16) unsigned char g_wpack[G * 16384];

__device__ __forceinline__ uint32_t swz(uint32_t off) {
    return off ^ ((off >> 3) & 0x70);
}
__device__ __forceinline__ uint32_t s2u(const void* p) {
    return (uint32_t)__cvta_generic_to_shared(p);
}
__device__ __forceinline__ void cp16(uint32_t d, const void* s) {
    asm volatile("cp.async.cg.shared.global [%0], [%1], 16;\n" :: "r"(d), "l"(s));
}
__device__ __forceinline__ void cp_commit() {
    asm volatile("cp.async.commit_group;\n");
}
template <int N>
__device__ __forceinline__ void cp_wait() {
    asm volatile("cp.async.wait_group %0;\n" :: "n"(N));
}
__device__ __forceinline__ void split2(float v0, float v1, uint32_t& hi, uint32_t& lo) {
    __nv_bfloat162 hp = __floats2bfloat162_rn(v0, v1);
    float r0 = v0 - __bfloat162float(hp.x);
    float r1 = v1 - __bfloat162float(hp.y);
    __nv_bfloat162 lp = __floats2bfloat162_rn(r0, r1);
    memcpy(&hi, &hp, 4); memcpy(&lo, &lp, 4);
}
__device__ __forceinline__ void mma16816(float* d,
    uint32_t a0, uint32_t a1, uint32_t a2, uint32_t a3, uint32_t b0, uint32_t b1)
{
    asm volatile("mma.sync.aligned.m16n8k16.row.col.f32.bf16.bf16.f32 "
        "{%0,%1,%2,%3}, {%4,%5,%6,%7}, {%8,%9}, {%0,%1,%2,%3};"
        : "+f"(d[0]), "+f"(d[1]), "+f"(d[2]), "+f"(d[3])
        : "r"(a0), "r"(a1), "r"(a2), "r"(a3), "r"(b0), "r"(b1));
}
__device__ __forceinline__ float sigmoidf(float b) {
    return 1.f / (1.f + __expf(-b));
}
__device__ __forceinline__ uint32_t lds32(const char* p) {
    return *(const uint32_t*)p;
}

// ---- pre-kernel: w fp32 [g][o][i] -> bf16 hi/lo swizzled B tiles ----
__global__ void pack_w_kernel(const float* __restrict__ w) {
    int f = blockIdx.x * blockDim.x + threadIdx.x;   // 0..16383 (word pairs)
    int g = f >> 11, rem = f & 2047;
    int o = rem >> 5, iw = rem & 31;                 // i = 2*iw
    const float* src = w + (((size_t)g * FO + o) * FI + 2 * iw);
    uint32_t hi, lo;
    split2(src[0], src[1], hi, lo);
    uint32_t boff = swz((uint32_t)(o * 128 + iw * 4));
    *(uint32_t*)(g_wpack + g * 16384 + boff)        = hi;
    *(uint32_t*)(g_wpack + g * 16384 + 8192 + boff) = lo;
}

__global__ __launch_bounds__(NTHREADS, 1)
void dynrout_hmma(const float* __restrict__ x, const float* __restrict__ bias,
                  float* __restrict__ out)
{
    extern __shared__ char smem[];
    float* sgram = (float*)smem;            // [2][64][36]

    const int tid = threadIdx.x;
    const int wid = tid >> 5, lid = tid & 31;
    const int b   = blockIdx.x >> 6;
    const int p0  = (blockIdx.x & 63) << 6;

    // producer roles (all threads)
    const int xpx = tid & 63;
    const int xi0 = (tid >> 6) << 4;

    // mma roles: 8 warps, m16 x n32 tiles; warp handles ALL groups
    const int gr = lid >> 2, tig = lid & 3;
    const int pb = (wid & 3) << 4;
    const int ob = (wid >> 2) << 5;
    const int slot = wid >> 2;              // o-half = gram slot

    const float* xbase = x + (size_t)b * C * HW + p0;
    float xr[16];

    auto ldx = [&](int g) {
        const float* xp = xbase + (size_t)g * FI * HW + xpx;
        #pragma unroll
        for (int k = 0; k < 16; k++) xr[k] = __ldg(xp + (size_t)(xi0 + k) * HW);
    };
    auto issueB = [&](int g, int buf) {
        const unsigned char* src = g_wpack + g * 16384;
        uint32_t d0 = s2u(smem + OFF_BUF + buf * BUFSZ + BHI);
        #pragma unroll
        for (int r = 0; r < 4; r++)
            cp16(d0 + (uint32_t)(r * 4096 + tid * 16), src + r * 4096 + tid * 16);
        cp_commit();
    };
    auto cvtA = [&](int buf) {
        char* bp = smem + OFF_BUF + buf * BUFSZ;
        uint32_t hi[8], lo[8];
        #pragma unroll
        for (int k = 0; k < 8; k++) split2(xr[2*k], xr[2*k+1], hi[k], lo[k]);
        uint32_t offA = (uint32_t)(xpx * 128 + xi0 * 2);
        *(uint4*)(bp + AHI + swz(offA))    = make_uint4(hi[0], hi[1], hi[2], hi[3]);
        *(uint4*)(bp + AHI + swz(offA+16)) = make_uint4(hi[4], hi[5], hi[6], hi[7]);
        *(uint4*)(bp + ALO + swz(offA))    = make_uint4(lo[0], lo[1], lo[2], lo[3]);
        *(uint4*)(bp + ALO + swz(offA+16)) = make_uint4(lo[4], lo[5], lo[6], lo[7]);
    };

    // con in registers: acc[g][jj][k]
    // o(jj,kk) = ob + 8*jj + 2*tig + kk ; p(k>>1) = pb + gr + 8*(k>>1)
    float acc[G][4][4];
    #pragma unroll
    for (int g = 0; g < G; g++)
        #pragma unroll
        for (int j = 0; j < 4; j++)
            #pragma unroll
            for (int k = 0; k < 4; k++) acc[g][j][k] = 0.f;

    auto mma_group = [&](int g, float (&a4)[4][4]) {
        const char* bp = smem + OFF_BUF + (g & 1) * BUFSZ;
        #pragma unroll
        for (int ks = 0; ks < 4; ks++) {
            uint32_t r0 = (uint32_t)((pb + gr)     * 128 + tig * 4 + ks * 32);
            uint32_t r1 = (uint32_t)((pb + gr + 8) * 128 + tig * 4 + ks * 32);
            uint32_t ah0 = lds32(bp + AHI + swz(r0));
            uint32_t ah1 = lds32(bp + AHI + swz(r1));
            uint32_t ah2 = lds32(bp + AHI + swz(r0 + 16));
            uint32_t ah3 = lds32(bp + AHI + swz(r1 + 16));
            uint32_t al0 = lds32(bp + ALO + swz(r0));
            uint32_t al1 = lds32(bp + ALO + swz(r1));
            uint32_t al2 = lds32(bp + ALO + swz(r0 + 16));
            uint32_t al3 = lds32(bp + ALO + swz(r1 + 16));
            #pragma unroll
            for (int jj = 0; jj < 4; jj++) {
                uint32_t rb = (uint32_t)((ob + 8 * jj + gr) * 128 + tig * 4 + ks * 32);
                uint32_t bh0 = lds32(bp + BHI + swz(rb));
                uint32_t bh1 = lds32(bp + BHI + swz(rb + 16));
                uint32_t bl0 = lds32(bp + BLO + swz(rb));
                uint32_t bl1 = lds32(bp + BLO + swz(rb + 16));
                mma16816(a4[jj], ah0, ah1, ah2, ah3, bh0, bh1);
                mma16816(a4[jj], ah0, ah1, ah2, ah3, bl0, bl1);
                mma16816(a4[jj], al0, al1, al2, al3, bh0, bh1);
            }
        }
    };

    // ---------------- pipelined conv (R13 ordering, unrolled for reg acc) ----
    issueB(0, 0);
    ldx(0);
    cvtA(0);

    #pragma unroll
    for (int g = 0; g < G; g++) {
        __syncthreads();                   // mma(g-1) done -> buf (g+1)&1 free
        if (g < G - 1) {
            issueB(g + 1, (g + 1) & 1);
            cp_wait<1>();                  // B(g) landed
        } else {
            cp_wait<0>();
        }
        __syncthreads();                   // B(g)+cvtA(g) visible to all
        if (g < G - 1) ldx(g + 1);
        mma_group(g, acc[g]);
        if (g < G - 1) cvtA((g + 1) & 1);
    }
    __syncthreads();

    // ---------------- Gram routing epilogue, register-resident con ----------
    {
        float Gm[36];
        // phase p2: pixel px = pb + gr + 8*p2 ; this thread's con values are
        // acc[g][jj][2*p2 + kk] for o = ob + 8*jj + 2*tig + kk
        #pragma unroll
        for (int p2 = 0; p2 < 2; p2++) {
            #pragma unroll
            for (int k = 0; k < 36; k++) Gm[k] = 0.f;
            #pragma unroll
            for (int jj = 0; jj < 4; jj++) {
                #pragma unroll
                for (int kk = 0; kk < 2; kk++) {
                    float c[G];
                    #pragma unroll
                    for (int g = 0; g < G; g++) c[g] = acc[g][jj][2 * p2 + kk];
                    int idx = 0;
                    #pragma unroll
                    for (int g = 0; g < G; g++)
                        #pragma unroll
                        for (int h = g; h < G; h++) {
                            Gm[idx] = fmaf(c[g], c[h], Gm[idx]);
                            idx++;
                        }
                }
            }
            // reduce over the 4 tig lanes (same px within warp)
            #pragma unroll
            for (int k = 0; k < 36; k++) {
                Gm[k] += __shfl_xor_sync(0xFFFFFFFFu, Gm[k], 1);
                Gm[k] += __shfl_xor_sync(0xFFFFFFFFu, Gm[k], 2);
            }
            // write this o-half's partial Gram: sgram[slot][px][idx]
            const int px = pb + gr + 8 * p2;
            float* dst = sgram + (slot * 64 + px) * 36;
            #pragma unroll
            for (int i = 0; i < 9; i++) dst[tig + 4 * i] = Gm[tig + 4 * i];
        }
        __syncthreads();

        // per-pixel routing iterations (sum both o-half Grams)
        float al[2][G];
        #pragma unroll
        for (int p2 = 0; p2 < 2; p2++) {
            const int px = pb + gr + 8 * p2;
            const float* s0 = sgram + px * 36;
            const float* s1 = sgram + (64 + px) * 36;
            #pragma unroll
            for (int k = 0; k < 36; k++) Gm[k] = s0[k] + s1[k];

            float beta[G];
            #pragma unroll
            for (int g = 0; g < G; g++) beta[g] = 0.f;
            #pragma unroll
            for (int it = 0; it < 2; it++) {
                float a_[G], d[G];
                #pragma unroll
                for (int g = 0; g < G; g++) { a_[g] = sigmoidf(beta[g]); d[g] = 0.f; }
                #pragma unroll
                for (int g = 0; g < G; g++) {
                    #pragma unroll
                    for (int h = 0; h < G; h++) {
                        const int lo2 = g < h ? g : h;
                        const int hi2 = g < h ? h : g;
                        const int idx = lo2 * G - (lo2 * (lo2 - 1)) / 2 + (hi2 - lo2);
                        d[g] = fmaf(a_[h], Gm[idx], d[g]);
                    }
                }
                #pragma unroll
                for (int g = 0; g < G; g++) beta[g] += d[g];
            }
            #pragma unroll
            for (int g = 0; g < G; g++) al[p2][g] = sigmoidf(beta[g]);
        }

        // final combine from registers + bias + store
        float* ob2 = out + (size_t)b * FO * HW + p0;
        #pragma unroll
        for (int jj = 0; jj < 4; jj++) {
            #pragma unroll
            for (int kk = 0; kk < 2; kk++) {
                const int o = ob + 8 * jj + 2 * tig + kk;
                const float bo = __ldg(bias + o);
                #pragma unroll
                for (int p2 = 0; p2 < 2; p2++) {
                    const int px = pb + gr + 8 * p2;
                    float vo = 0.f;
                    #pragma unroll
                    for (int g = 0; g < G; g++)
                        vo = fmaf(al[p2][g], acc[g][jj][2 * p2 + kk], vo);
                    ob2[(size_t)o * HW + px] = vo + bo;
                }
            }
        }
    }
}

extern "C" void kernel_launch(void* const* d_in, const int* in_sizes, int n_in,
                              void* d_out, int out_size)
{
    const float* x    = (const float*)d_in[0];
    const float* wgt  = (const float*)d_in[1];
    const float* bias = (const float*)d_in[2];
    float* out        = (float*)d_out;

    static int attr_set = 0;
    if (!attr_set) {
        cudaFuncSetAttribute(dynrout_hmma,
                             cudaFuncAttributeMaxDynamicSharedMemorySize, SMEM_TOTAL);
        attr_set = 1;
    }

    pack_w_kernel<<<64, 256>>>(wgt);
    dim3 grid(BSZ * (HW / TP));            // 2048
    dynrout_hmma<<<grid, NTHREADS, SMEM_TOTAL>>>(x, bias, out);
}

// round 15
// speedup vs baseline: 1.3005x; 1.3005x over previous
#include <cuda_runtime.h>
#include <cuda_fp16.h>
#include <cstdint>
#include <cstring>

// DynamicRouting: grouped 1x1 conv via SINGLE-PASS fp16 mma.sync (fp32 accum)
// + fused register-only Gram routing epilogue. 256 thr / 8 warps, m16n32 tiles,
// double-buffered operand tiles, weights pre-packed to fp16 by a pre-kernel.

#define G   8
#define FO  64
#define FI  64
#define HW  4096
#define C   512
#define BSZ 32
#define TP  64
#define NTHREADS 256

#define CPAD 65
#define CONG (FO*CPAD)                 // 4160 floats per group
#define OFF_BUF (G*CONG*4)             // 133120 B
#define BUFSZ   16384                  // [A 8K | B 8K] fp16 tiles
#define AOF 0
#define BOF 8192
#define SMEM_TOTAL (OFF_BUF + 2*BUFSZ) // 165888 B

// packed weights: per group 8KB fp16, swizzled B-tile layout
__device__ __align__(16) unsigned char g_wpack[G * 8192];

__device__ __forceinline__ uint32_t swz(uint32_t off) {
    return off ^ ((off >> 3) & 0x70);
}
__device__ __forceinline__ uint32_t s2u(const void* p) {
    return (uint32_t)__cvta_generic_to_shared(p);
}
__device__ __forceinline__ void cp16(uint32_t d, const void* s) {
    asm volatile("cp.async.cg.shared.global [%0], [%1], 16;\n" :: "r"(d), "l"(s));
}
__device__ __forceinline__ void cp_commit() {
    asm volatile("cp.async.commit_group;\n");
}
template <int N>
__device__ __forceinline__ void cp_wait() {
    asm volatile("cp.async.wait_group %0;\n" :: "n"(N));
}
__device__ __forceinline__ uint32_t h2pack(float v0, float v1) {
    __half2 h = __floats2half2_rn(v0, v1);
    uint32_t r; memcpy(&r, &h, 4); return r;
}
__device__ __forceinline__ void mma16816(float* d,
    uint32_t a0, uint32_t a1, uint32_t a2, uint32_t a3, uint32_t b0, uint32_t b1)
{
    asm volatile("mma.sync.aligned.m16n8k16.row.col.f32.f16.f16.f32 "
        "{%0,%1,%2,%3}, {%4,%5,%6,%7}, {%8,%9}, {%0,%1,%2,%3};"
        : "+f"(d[0]), "+f"(d[1]), "+f"(d[2]), "+f"(d[3])
        : "r"(a0), "r"(a1), "r"(a2), "r"(a3), "r"(b0), "r"(b1));
}
__device__ __forceinline__ float sigmoidf(float b) {
    return 1.f / (1.f + __expf(-b));
}
__device__ __forceinline__ uint32_t lds32(const char* p) {
    return *(const uint32_t*)p;
}

// ---- pre-kernel: w fp32 [g][o][i] -> fp16 swizzled B tiles ----
__global__ void pack_w_kernel(const float* __restrict__ w) {
    int f = blockIdx.x * blockDim.x + threadIdx.x;   // 0..16383 (word pairs)
    int g = f >> 11, rem = f & 2047;
    int o = rem >> 5, iw = rem & 31;                 // i = 2*iw
    const float* src = w + (((size_t)g * FO + o) * FI + 2 * iw);
    uint32_t hv = h2pack(src[0], src[1]);
    uint32_t boff = swz((uint32_t)(o * 128 + iw * 4));
    *(uint32_t*)(g_wpack + g * 8192 + boff) = hv;
}

__global__ __launch_bounds__(NTHREADS, 1)
void dynrout_hmma(const float* __restrict__ x, const float* __restrict__ bias,
                  float* __restrict__ out)
{
    extern __shared__ char smem[];
    float* con = (float*)smem;

    const int tid = threadIdx.x;
    const int wid = tid >> 5, lid = tid & 31;
    const int b   = blockIdx.x >> 6;
    const int p0  = (blockIdx.x & 63) << 6;

    // producer roles (all 256 threads)
    const int xpx = tid & 63;               // A row (pixel)
    const int xi0 = (tid >> 6) << 4;        // 16 i's per thread

    // mma roles: 8 warps, m16 x n32 tiles (R13)
    const int gr = lid >> 2, tig = lid & 3;
    const int pb = (wid & 3) << 4;          // px tile base
    const int ob = (wid >> 2) << 5;         // o tile base (32 o's)

    const float* xbase = x + (size_t)b * C * HW + p0;
    float xr[16];

    auto ldx = [&](int g) {
        const float* xp = xbase + (size_t)g * FI * HW + xpx;
        #pragma unroll
        for (int k = 0; k < 16; k++) xr[k] = __ldg(xp + (size_t)(xi0 + k) * HW);
    };
    auto issueB = [&](int g, int buf) {      // 8KB coalesced fp16 tile
        const unsigned char* src = g_wpack + g * 8192;
        uint32_t d0 = s2u(smem + OFF_BUF + buf * BUFSZ + BOF);
        #pragma unroll
        for (int r = 0; r < 2; r++)
            cp16(d0 + (uint32_t)(r * 4096 + tid * 16), src + r * 4096 + tid * 16);
        cp_commit();
    };
    auto cvtA = [&](int buf) {
        char* bp = smem + OFF_BUF + buf * BUFSZ;
        uint32_t hv[8];
        #pragma unroll
        for (int k = 0; k < 8; k++) hv[k] = h2pack(xr[2*k], xr[2*k+1]);
        uint32_t offA = (uint32_t)(xpx * 128 + xi0 * 2);
        *(uint4*)(bp + AOF + swz(offA))    = make_uint4(hv[0], hv[1], hv[2], hv[3]);
        *(uint4*)(bp + AOF + swz(offA+16)) = make_uint4(hv[4], hv[5], hv[6], hv[7]);
    };

    auto mma_group = [&](int g) {
        const char* bp = smem + OFF_BUF + (g & 1) * BUFSZ;
        float acc[4][4];
        #pragma unroll
        for (int j = 0; j < 4; j++)
            #pragma unroll
            for (int k = 0; k < 4; k++) acc[j][k] = 0.f;

        #pragma unroll
        for (int ks = 0; ks < 4; ks++) {
            uint32_t r0 = (uint32_t)((pb + gr)     * 128 + tig * 4 + ks * 32);
            uint32_t r1 = (uint32_t)((pb + gr + 8) * 128 + tig * 4 + ks * 32);
            uint32_t a0 = lds32(bp + AOF + swz(r0));
            uint32_t a1 = lds32(bp + AOF + swz(r1));
            uint32_t a2 = lds32(bp + AOF + swz(r0 + 16));
            uint32_t a3 = lds32(bp + AOF + swz(r1 + 16));
            #pragma unroll
            for (int jj = 0; jj < 4; jj++) {
                uint32_t rb = (uint32_t)((ob + 8 * jj + gr) * 128 + tig * 4 + ks * 32);
                uint32_t b0 = lds32(bp + BOF + swz(rb));
                uint32_t b1 = lds32(bp + BOF + swz(rb + 16));
                mma16816(acc[jj], a0, a1, a2, a3, b0, b1);
            }
        }
        float* cg = con + g * CONG;
        #pragma unroll
        for (int jj = 0; jj < 4; jj++) {
            int o0  = ob + 8 * jj + 2 * tig;
            int px0 = pb + gr;
            cg[(size_t)o0       * CPAD + px0]     = acc[jj][0];
            cg[(size_t)(o0 + 1) * CPAD + px0]     = acc[jj][1];
            cg[(size_t)o0       * CPAD + px0 + 8] = acc[jj][2];
            cg[(size_t)(o0 + 1) * CPAD + px0 + 8] = acc[jj][3];
        }
    };

    // ---------------- race-free pipelined conv (R13 ordering) ----------------
    issueB(0, 0);
    ldx(0);
    cvtA(0);

    for (int g = 0; g < G; g++) {
        __syncthreads();                   // mma(g-1) done -> buf (g+1)&1 free
        if (g < G - 1) {
            issueB(g + 1, (g + 1) & 1);
            cp_wait<1>();                  // B(g) landed
        } else {
            cp_wait<0>();
        }
        __syncthreads();                   // B(g)+cvtA(g) visible to all
        if (g < G - 1) ldx(g + 1);
        mma_group(g);
        if (g < G - 1) cvtA((g + 1) & 1);
    }
    __syncthreads();

    // -------- Gram routing epilogue: 256 thr = 64 px x 4 o-lanes (R13) -------
    {
        const int p  = tid >> 2;           // pixel
        const int oq = tid & 3;            // o-partition lane
        const float* conp = con + p;
        // o(j) = 8*oq + (j&7) + 32*(j>>3): bank-clean for fixed p

        float Gm[36];
        #pragma unroll
        for (int k = 0; k < 36; k++) Gm[k] = 0.f;

        #pragma unroll
        for (int j = 0; j < 16; j++) {
            const int o = 8 * oq + (j & 7) + 32 * (j >> 3);
            float c[G];
            #pragma unroll
            for (int g = 0; g < G; g++) c[g] = conp[g * CONG + o * CPAD];
            int idx = 0;
            #pragma unroll
            for (int g = 0; g < G; g++)
                #pragma unroll
                for (int h = g; h < G; h++) {
                    Gm[idx] = fmaf(c[g], c[h], Gm[idx]);
                    idx++;
                }
        }
        // reduce Gram over the 4 same-pixel lanes
        #pragma unroll
        for (int k = 0; k < 36; k++) {
            Gm[k] += __shfl_xor_sync(0xFFFFFFFFu, Gm[k], 1);
            Gm[k] += __shfl_xor_sync(0xFFFFFFFFu, Gm[k], 2);
        }

        // register-only routing iterations
        float beta[G];
        #pragma unroll
        for (int g = 0; g < G; g++) beta[g] = 0.f;
        #pragma unroll
        for (int it = 0; it < 2; it++) {
            float al[G], d[G];
            #pragma unroll
            for (int g = 0; g < G; g++) { al[g] = sigmoidf(beta[g]); d[g] = 0.f; }
            #pragma unroll
            for (int g = 0; g < G; g++) {
                #pragma unroll
                for (int h = 0; h < G; h++) {
                    const int lo2 = g < h ? g : h;
                    const int hi2 = g < h ? h : g;
                    const int idx = lo2 * G - (lo2 * (lo2 - 1)) / 2 + (hi2 - lo2);
                    d[g] = fmaf(al[h], Gm[idx], d[g]);
                }
            }
            #pragma unroll
            for (int g = 0; g < G; g++) beta[g] += d[g];
        }
        float al[G];
        #pragma unroll
        for (int g = 0; g < G; g++) al[g] = sigmoidf(beta[g]);

        // final combine + bias + store
        float* ob2 = out + (size_t)b * FO * HW + p0 + p;
        #pragma unroll
        for (int j = 0; j < 16; j++) {
            const int o = 8 * oq + (j & 7) + 32 * (j >> 3);
            float vo = 0.f;
            #pragma unroll
            for (int g = 0; g < G; g++)
                vo = fmaf(al[g], conp[g * CONG + o * CPAD], vo);
            ob2[(size_t)o * HW] = vo + __ldg(bias + o);
        }
    }
}

extern "C" void kernel_launch(void* const* d_in, const int* in_sizes, int n_in,
                              void* d_out, int out_size)
{
    const float* x    = (const float*)d_in[0];
    const float* wgt  = (const float*)d_in[1];
    const float* bias = (const float*)d_in[2];
    float* out        = (float*)d_out;

    static int attr_set = 0;
    if (!attr_set) {
        cudaFuncSetAttribute(dynrout_hmma,
                             cudaFuncAttributeMaxDynamicSharedMemorySize, SMEM_TOTAL);
        attr_set = 1;
    }

    pack_w_kernel<<<64, 256>>>(wgt);
    dim3 grid(BSZ * (HW / TP));            // 2048
    dynrout_hmma<<<grid, NTHREADS, SMEM_TOTAL>>>(x, bias, out);
}